// round 1
// baseline (speedup 1.0000x reference)
#include <cuda_runtime.h>
#include <math.h>

// Problem constants
#define Bq  4
#define Hh  64
#define Ww  64
#define Cc  128
#define NHh 4
#define Kk  7
#define HDd 32
#define MLPD 512
#define NTOK (Bq*Hh*Ww)   // 16384

// Scratch (device globals — no allocation allowed in kernel_launch)
__device__ float g_qn    [NTOK*Cc];
__device__ float g_kvn   [NTOK*Cc];
__device__ float g_q     [NTOK*Cc];
__device__ float g_kv    [NTOK*2*Cc];
__device__ float g_attn  [NTOK*Cc];
__device__ float g_x     [NTOK*Cc];
__device__ float g_hln   [NTOK*Cc];
__device__ float g_hidden[NTOK*MLPD];

// ---------------------------------------------------------------------------
// LayerNorm: one warp per token (C=128, lane handles 4 contiguous floats)
// ---------------------------------------------------------------------------
__global__ void ln_kernel(const float* __restrict__ in,
                          const float* __restrict__ g,
                          const float* __restrict__ b,
                          float* __restrict__ out, int ntok)
{
    int warp = (blockIdx.x * blockDim.x + threadIdx.x) >> 5;
    int lane = threadIdx.x & 31;
    if (warp >= ntok) return;

    const float4 v = *(const float4*)&in[warp*Cc + lane*4];
    float s  = v.x + v.y + v.z + v.w;
    float sq = v.x*v.x + v.y*v.y + v.z*v.z + v.w*v.w;
    #pragma unroll
    for (int off = 16; off; off >>= 1) {
        s  += __shfl_xor_sync(0xffffffff, s,  off);
        sq += __shfl_xor_sync(0xffffffff, sq, off);
    }
    float mean = s * (1.0f/Cc);
    float var  = sq * (1.0f/Cc) - mean*mean;
    float inv  = rsqrtf(var + 1e-5f);

    const float4 gv = *(const float4*)&g[lane*4];
    const float4 bv = *(const float4*)&b[lane*4];
    float4 o;
    o.x = (v.x - mean)*inv*gv.x + bv.x;
    o.y = (v.y - mean)*inv*gv.y + bv.y;
    o.z = (v.z - mean)*inv*gv.z + bv.z;
    o.w = (v.w - mean)*inv*gv.w + bv.w;
    *(float4*)&out[warp*Cc + lane*4] = o;
}

// ---------------------------------------------------------------------------
// Generic fp32 GEMM: C = epilogue(A[MxK] @ W[KxN] + bias)
//   MODE 0: +bias
//   MODE 1: (+bias) * scale          (for Q)
//   MODE 2: gelu(+bias)              (exact erf gelu)
//   MODE 3: +bias + residual[MxN]
// BM=BN=64, BK=16, 256 threads, 4x4 per thread. M,N,K divisible by tiles.
// ---------------------------------------------------------------------------
template <int MODE>
__global__ void gemm_kernel(const float* __restrict__ A,
                            const float* __restrict__ W,
                            const float* __restrict__ bias,
                            const float* __restrict__ res,
                            float* __restrict__ C,
                            int M, int N, int K, float scale)
{
    __shared__ float As[16][64];   // [k][m]
    __shared__ float Ws[16][64];   // [k][n]

    const int bm = blockIdx.y * 64;
    const int bn = blockIdx.x * 64;
    const int tid = threadIdx.x;          // 0..255
    const int ty = tid >> 4;              // 0..15
    const int tx = tid & 15;              // 0..15

    float acc[4][4];
    #pragma unroll
    for (int m = 0; m < 4; m++)
        #pragma unroll
        for (int n = 0; n < 4; n++) acc[m][n] = 0.0f;

    const int ar = tid >> 2;               // 0..63
    const int ac = (tid & 3) << 2;         // 0,4,8,12
    const int wr = tid >> 4;               // 0..15
    const int wc = (tid & 15) << 2;        // 0..60

    for (int k0 = 0; k0 < K; k0 += 16) {
        float4 av = *(const float4*)&A[(size_t)(bm + ar)*K + k0 + ac];
        As[ac+0][ar] = av.x;
        As[ac+1][ar] = av.y;
        As[ac+2][ar] = av.z;
        As[ac+3][ar] = av.w;
        float4 wv = *(const float4*)&W[(size_t)(k0 + wr)*N + bn + wc];
        *(float4*)&Ws[wr][wc] = wv;
        __syncthreads();

        #pragma unroll
        for (int kk = 0; kk < 16; kk++) {
            float a[4], b[4];
            #pragma unroll
            for (int m = 0; m < 4; m++) a[m] = As[kk][ty*4 + m];
            #pragma unroll
            for (int n = 0; n < 4; n++) b[n] = Ws[kk][tx*4 + n];
            #pragma unroll
            for (int m = 0; m < 4; m++)
                #pragma unroll
                for (int n = 0; n < 4; n++)
                    acc[m][n] = fmaf(a[m], b[n], acc[m][n]);
        }
        __syncthreads();
    }

    #pragma unroll
    for (int m = 0; m < 4; m++) {
        int row = bm + ty*4 + m;
        #pragma unroll
        for (int n = 0; n < 4; n++) {
            int col = bn + tx*4 + n;
            float v = acc[m][n] + bias[col];
            if (MODE == 1) v *= scale;
            if (MODE == 2) v = 0.5f * v * (1.0f + erff(v * 0.70710678118654752f));
            if (MODE == 3) v += res[(size_t)row*N + col];
            C[(size_t)row*N + col] = v;
        }
    }
}

// ---------------------------------------------------------------------------
// Neighborhood attention. One block per token (b,i,j), 4 warps = 4 heads.
// q buffer:   [tok, h*32+d]       (already scaled by HD^-0.5)
// kv buffer:  [tok, sel*128 + h*32 + d]  (sel 0 = K, sel 1 = V)
// rpb:        [NH, 13, 13]
// out:        [tok, h*32+d]
// ---------------------------------------------------------------------------
__global__ void nat_attn_kernel(const float* __restrict__ q,
                                const float* __restrict__ kv,
                                const float* __restrict__ rpb,
                                float* __restrict__ out)
{
    const int t = blockIdx.x;
    const int b = t / (Hh*Ww);
    const int ij = t % (Hh*Ww);
    const int i = ij / Ww;
    const int j = ij % Ww;

    const int h    = threadIdx.x >> 5;
    const int lane = threadIdx.x & 31;

    int i0 = i - Kk/2; if (i0 < 0) i0 = 0; if (i0 > Hh - Kk) i0 = Hh - Kk;
    int j0 = j - Kk/2; if (j0 < 0) j0 = 0; if (j0 > Ww - Kk) j0 = Ww - Kk;

    __shared__ float sc[NHh][56];   // 49 scores per head (padded)

    const float qd = q[(size_t)t*Cc + h*HDd + lane];
    const int base_tok = b*Hh*Ww;

    // scores
    for (int n = 0; n < Kk*Kk; n++) {
        int ni = n / Kk, nj = n % Kk;
        int nbr = base_tok + (i0 + ni)*Ww + (j0 + nj);
        float val = qd * kv[(size_t)nbr*(2*Cc) + h*HDd + lane];
        #pragma unroll
        for (int off = 16; off; off >>= 1)
            val += __shfl_xor_sync(0xffffffff, val, off);
        if (lane == 0) {
            int ri = i0 + ni - i + (Kk - 1);
            int rj = j0 + nj - j + (Kk - 1);
            sc[h][n] = val + rpb[h*(2*Kk-1)*(2*Kk-1) + ri*(2*Kk-1) + rj];
        }
    }
    __syncwarp();

    // softmax over 49 (lane handles n=lane and n=lane+32)
    float s0 = (lane < 49) ? sc[h][lane] : -INFINITY;
    float s1 = (lane + 32 < 49) ? sc[h][lane + 32] : -INFINITY;
    float mx = fmaxf(s0, s1);
    #pragma unroll
    for (int off = 16; off; off >>= 1)
        mx = fmaxf(mx, __shfl_xor_sync(0xffffffff, mx, off));
    float e0 = (lane < 49) ? __expf(s0 - mx) : 0.0f;
    float e1 = (lane + 32 < 49) ? __expf(s1 - mx) : 0.0f;
    float sum = e0 + e1;
    #pragma unroll
    for (int off = 16; off; off >>= 1)
        sum += __shfl_xor_sync(0xffffffff, sum, off);
    float rinv = 1.0f / sum;
    if (lane < 49)       sc[h][lane]      = e0 * rinv;
    if (lane + 32 < 49)  sc[h][lane + 32] = e1 * rinv;
    __syncwarp();

    // weighted sum of V
    float acc = 0.0f;
    for (int n = 0; n < Kk*Kk; n++) {
        int ni = n / Kk, nj = n % Kk;
        int nbr = base_tok + (i0 + ni)*Ww + (j0 + nj);
        acc = fmaf(sc[h][n], kv[(size_t)nbr*(2*Cc) + Cc + h*HDd + lane], acc);
    }
    out[(size_t)t*Cc + h*HDd + lane] = acc;
}

// ---------------------------------------------------------------------------
// Launch
// ---------------------------------------------------------------------------
extern "C" void kernel_launch(void* const* d_in, const int* in_sizes, int n_in,
                              void* d_out, int out_size)
{
    const float* query     = (const float*)d_in[0];
    const float* key_value = (const float*)d_in[1];
    const float* g1  = (const float*)d_in[2];
    const float* b1  = (const float*)d_in[3];
    const float* g2  = (const float*)d_in[4];
    const float* b2  = (const float*)d_in[5];
    const float* g3  = (const float*)d_in[6];
    const float* b3  = (const float*)d_in[7];
    const float* Wq  = (const float*)d_in[8];
    const float* bq  = (const float*)d_in[9];
    const float* Wkv = (const float*)d_in[10];
    const float* bkv = (const float*)d_in[11];
    const float* Wp  = (const float*)d_in[12];
    const float* bp  = (const float*)d_in[13];
    const float* rpb = (const float*)d_in[14];
    const float* W1  = (const float*)d_in[15];
    const float* bm1 = (const float*)d_in[16];
    const float* W2  = (const float*)d_in[17];
    const float* bm2 = (const float*)d_in[18];
    float* out = (float*)d_out;

    float* qn     = nullptr; cudaGetSymbolAddress((void**)&qn,     g_qn);
    float* kvn    = nullptr; cudaGetSymbolAddress((void**)&kvn,    g_kvn);
    float* qbuf   = nullptr; cudaGetSymbolAddress((void**)&qbuf,   g_q);
    float* kvbuf  = nullptr; cudaGetSymbolAddress((void**)&kvbuf,  g_kv);
    float* attn   = nullptr; cudaGetSymbolAddress((void**)&attn,   g_attn);
    float* xbuf   = nullptr; cudaGetSymbolAddress((void**)&xbuf,   g_x);
    float* hln    = nullptr; cudaGetSymbolAddress((void**)&hln,    g_hln);
    float* hidden = nullptr; cudaGetSymbolAddress((void**)&hidden, g_hidden);

    const int lnBlocks = (NTOK * 32) / 256;   // 8 tokens per block

    // 1) LayerNorms of query and key_value
    ln_kernel<<<lnBlocks, 256>>>(query,     g1, b1, qn,  NTOK);
    ln_kernel<<<lnBlocks, 256>>>(key_value, g2, b2, kvn, NTOK);

    // 2) Q projection (scaled) and KV projection
    gemm_kernel<1><<<dim3(Cc/64,   NTOK/64), 256>>>(qn,  Wq,  bq,  nullptr, qbuf,  NTOK, Cc,   Cc, 0.17677669529663689f);
    gemm_kernel<0><<<dim3(2*Cc/64, NTOK/64), 256>>>(kvn, Wkv, bkv, nullptr, kvbuf, NTOK, 2*Cc, Cc, 1.0f);

    // 3) Neighborhood attention
    nat_attn_kernel<<<NTOK, NHh*32>>>(qbuf, kvbuf, rpb, attn);

    // 4) Output projection + residual (shortcut = key_value)
    gemm_kernel<3><<<dim3(Cc/64, NTOK/64), 256>>>(attn, Wp, bp, key_value, xbuf, NTOK, Cc, Cc, 1.0f);

    // 5) LN3 + MLP
    ln_kernel<<<lnBlocks, 256>>>(xbuf, g3, b3, hln, NTOK);
    gemm_kernel<2><<<dim3(MLPD/64, NTOK/64), 256>>>(hln,    W1, bm1, nullptr, hidden, NTOK, MLPD, Cc,   1.0f);
    gemm_kernel<3><<<dim3(Cc/64,   NTOK/64), 256>>>(hidden, W2, bm2, xbuf,    out,    NTOK, Cc,   MLPD, 1.0f);
}

// round 2
// speedup vs baseline: 1.2611x; 1.2611x over previous
#include <cuda_runtime.h>
#include <math.h>

// Problem constants
#define Bq  4
#define Hh  64
#define Ww  64
#define Cc  128
#define NHh 4
#define Kk  7
#define HDd 32
#define MLPD 512
#define NTOK (Bq*Hh*Ww)   // 16384

typedef unsigned long long ull;

// Scratch (device globals — no allocation allowed in kernel_launch)
__device__ float g_qn    [NTOK*Cc];
__device__ float g_kvn   [NTOK*Cc];
__device__ float g_q     [NTOK*Cc];
__device__ float g_kv    [NTOK*2*Cc];
__device__ float g_attn  [NTOK*Cc];
__device__ float g_x     [NTOK*Cc];
__device__ float g_hln   [NTOK*Cc];
__device__ float g_hidden[NTOK*MLPD];

#define FMA_F32X2(d,a,b,c) asm("fma.rn.f32x2 %0, %1, %2, %3;" : "=l"(d) : "l"(a), "l"(b), "l"(c))

// ---------------------------------------------------------------------------
// LayerNorm: one warp per token (C=128, lane handles 4 contiguous floats)
// ---------------------------------------------------------------------------
__global__ void ln_kernel(const float* __restrict__ in,
                          const float* __restrict__ g,
                          const float* __restrict__ b,
                          float* __restrict__ out, int ntok)
{
    int warp = (blockIdx.x * blockDim.x + threadIdx.x) >> 5;
    int lane = threadIdx.x & 31;
    if (warp >= ntok) return;

    const float4 v = *(const float4*)&in[(size_t)warp*Cc + lane*4];
    float s  = v.x + v.y + v.z + v.w;
    float sq = v.x*v.x + v.y*v.y + v.z*v.z + v.w*v.w;
    #pragma unroll
    for (int off = 16; off; off >>= 1) {
        s  += __shfl_xor_sync(0xffffffff, s,  off);
        sq += __shfl_xor_sync(0xffffffff, sq, off);
    }
    float mean = s * (1.0f/Cc);
    float var  = sq * (1.0f/Cc) - mean*mean;
    float inv  = rsqrtf(var + 1e-5f);

    const float4 gv = *(const float4*)&g[lane*4];
    const float4 bv = *(const float4*)&b[lane*4];
    float4 o;
    o.x = (v.x - mean)*inv*gv.x + bv.x;
    o.y = (v.y - mean)*inv*gv.y + bv.y;
    o.z = (v.z - mean)*inv*gv.z + bv.z;
    o.w = (v.w - mean)*inv*gv.w + bv.w;
    *(float4*)&out[(size_t)warp*Cc + lane*4] = o;
}

// ---------------------------------------------------------------------------
// fp32 GEMM with FFMA2 (fma.rn.f32x2): C = epilogue(A[MxK] @ W[KxN] + bias)
//   MODE 0: +bias
//   MODE 1: (+bias) * scale
//   MODE 2: gelu(+bias)  (exact erf gelu)
//   MODE 3: +bias + residual[MxN]
// BM=128, BN=128, BK=16, 256 threads, 8x8 per thread (m paired for f32x2).
// W is stored DUPLICATED in smem so {b,b} is a single LDS.64.
// Requires M%128==0, N%128==0, K%16==0.
// ---------------------------------------------------------------------------
template <int MODE>
__global__ __launch_bounds__(256)
void gemm_kernel(const float* __restrict__ A,
                 const float* __restrict__ W,
                 const float* __restrict__ bias,
                 const float* __restrict__ res,
                 float* __restrict__ C,
                 int M, int N, int K, float scale)
{
    __shared__ float As [2][16][128];
    __shared__ float Wsd[2][16][256];   // duplicated pairs

    const int bm = blockIdx.y * 128;
    const int bn = blockIdx.x * 128;
    const int tid = threadIdx.x;

    // load mappings
    const int ar = tid >> 1;              // 0..127 (A row)
    const int ak = (tid & 1) * 8;         // 0 or 8 (A k-offset)
    const int wr = tid >> 4;              // 0..15  (W k-row)
    const int wn = (tid & 15) * 8;        // 0..120 (W n-base)

    // compute mapping
    const int tx = tid & 15;              // n group
    const int ty = tid >> 4;              // m group

    const float* Aptr = A + (size_t)(bm + ar) * K + ak;
    const float* Wptr = W + (size_t)wr * N + bn + wn;

    ull acc2[4][8];
    #pragma unroll
    for (int p = 0; p < 4; p++)
        #pragma unroll
        for (int j = 0; j < 8; j++) acc2[p][j] = 0ull;

    const int nt = K / 16;

    // prologue: tile 0
    float4 av0 = *(const float4*)(Aptr);
    float4 av1 = *(const float4*)(Aptr + 4);
    float4 wv0 = *(const float4*)(Wptr);
    float4 wv1 = *(const float4*)(Wptr + 4);

    {
        As[0][ak+0][ar] = av0.x; As[0][ak+1][ar] = av0.y;
        As[0][ak+2][ar] = av0.z; As[0][ak+3][ar] = av0.w;
        As[0][ak+4][ar] = av1.x; As[0][ak+5][ar] = av1.y;
        As[0][ak+6][ar] = av1.z; As[0][ak+7][ar] = av1.w;
        float4 d0 = make_float4(wv0.x, wv0.x, wv0.y, wv0.y);
        float4 d1 = make_float4(wv0.z, wv0.z, wv0.w, wv0.w);
        float4 d2 = make_float4(wv1.x, wv1.x, wv1.y, wv1.y);
        float4 d3 = make_float4(wv1.z, wv1.z, wv1.w, wv1.w);
        *(float4*)&Wsd[0][wr][2*wn +  0] = d0;
        *(float4*)&Wsd[0][wr][2*wn +  4] = d1;
        *(float4*)&Wsd[0][wr][2*wn +  8] = d2;
        *(float4*)&Wsd[0][wr][2*wn + 12] = d3;
    }
    __syncthreads();

    for (int t = 0; t < nt; t++) {
        const int cur = t & 1;
        const int nxt = cur ^ 1;
        if (t + 1 < nt) {
            const float* Ap = Aptr + (t + 1) * 16;
            const float* Wp = Wptr + (size_t)(t + 1) * 16 * N;
            av0 = *(const float4*)(Ap);
            av1 = *(const float4*)(Ap + 4);
            wv0 = *(const float4*)(Wp);
            wv1 = *(const float4*)(Wp + 4);
        }

        #pragma unroll
        for (int kk = 0; kk < 16; kk++) {
            ull a2[4], b2[8];
            a2[0] = *(const ull*)&As[cur][kk][ty*4 + 0];
            a2[1] = *(const ull*)&As[cur][kk][ty*4 + 2];
            a2[2] = *(const ull*)&As[cur][kk][64 + ty*4 + 0];
            a2[3] = *(const ull*)&As[cur][kk][64 + ty*4 + 2];
            #pragma unroll
            for (int j = 0; j < 8; j++)
                b2[j] = *(const ull*)&Wsd[cur][kk][2*(tx + 16*j)];
            #pragma unroll
            for (int p = 0; p < 4; p++)
                #pragma unroll
                for (int j = 0; j < 8; j++)
                    FMA_F32X2(acc2[p][j], a2[p], b2[j], acc2[p][j]);
        }

        if (t + 1 < nt) {
            As[nxt][ak+0][ar] = av0.x; As[nxt][ak+1][ar] = av0.y;
            As[nxt][ak+2][ar] = av0.z; As[nxt][ak+3][ar] = av0.w;
            As[nxt][ak+4][ar] = av1.x; As[nxt][ak+5][ar] = av1.y;
            As[nxt][ak+6][ar] = av1.z; As[nxt][ak+7][ar] = av1.w;
            float4 d0 = make_float4(wv0.x, wv0.x, wv0.y, wv0.y);
            float4 d1 = make_float4(wv0.z, wv0.z, wv0.w, wv0.w);
            float4 d2 = make_float4(wv1.x, wv1.x, wv1.y, wv1.y);
            float4 d3 = make_float4(wv1.z, wv1.z, wv1.w, wv1.w);
            *(float4*)&Wsd[nxt][wr][2*wn +  0] = d0;
            *(float4*)&Wsd[nxt][wr][2*wn +  4] = d1;
            *(float4*)&Wsd[nxt][wr][2*wn +  8] = d2;
            *(float4*)&Wsd[nxt][wr][2*wn + 12] = d3;
        }
        __syncthreads();
    }

    // epilogue
    float breg[8];
    #pragma unroll
    for (int j = 0; j < 8; j++) breg[j] = bias[bn + tx + 16*j];

    const int rowbase[4] = { ty*4, ty*4 + 2, 64 + ty*4, 64 + ty*4 + 2 };
    #pragma unroll
    for (int p = 0; p < 4; p++) {
        #pragma unroll
        for (int half = 0; half < 2; half++) {
            int row = bm + rowbase[p] + half;
            #pragma unroll
            for (int j = 0; j < 8; j++) {
                unsigned bits = half ? (unsigned)(acc2[p][j] >> 32)
                                     : (unsigned)(acc2[p][j] & 0xffffffffu);
                float v = __uint_as_float(bits) + breg[j];
                int col = bn + tx + 16*j;
                if (MODE == 1) v *= scale;
                if (MODE == 2) v = 0.5f * v * (1.0f + erff(v * 0.70710678118654752f));
                if (MODE == 3) v += res[(size_t)row*N + col];
                C[(size_t)row*N + col] = v;
            }
        }
    }
}

// ---------------------------------------------------------------------------
// Neighborhood attention, tiled: one block = 8 queries (same batch, same row i,
// consecutive j), 512 threads. KV patch (7 x 14 tokens, all heads) staged in
// dynamic SMEM once and reused by all 8 queries x 4 heads.
// q buffer:   [tok, h*32+d]  (pre-scaled by HD^-0.5)
// kv buffer:  [tok, sel*128 + h*32 + d] (sel 0 = K, sel 1 = V)
// ---------------------------------------------------------------------------
#define PATCH_TOK 98            // 7 * 14
#define KPAD 36                 // padded row (33 min, 16B aligned)
#define AT_THREADS 512

__global__ __launch_bounds__(AT_THREADS)
void nat_attn_kernel(const float* __restrict__ q,
                     const float* __restrict__ kv,
                     const float* __restrict__ rpb,
                     float* __restrict__ out)
{
    extern __shared__ float sm[];
    float* Ks = sm;                                   // [4][98][36]
    float* Vs = Ks + 4*PATCH_TOK*KPAD;                // [4][98][36]
    float* qs = Vs + 4*PATCH_TOK*KPAD;                // [8][128]
    float* ps = qs + 8*128;                           // [32][52]
    float* rs = ps + 32*52;                           // [676]

    const int blk = blockIdx.x;           // 0..2047
    const int b   = blk >> 9;             // 512 blocks per batch
    const int rem = blk & 511;
    const int i   = rem >> 3;
    const int jt  = (rem & 7) << 3;

    int i0  = i - 3;  if (i0 < 0) i0 = 0;  if (i0 > Hh - Kk) i0 = Hh - Kk;
    int jp0 = jt - 3; if (jp0 < 0) jp0 = 0; if (jp0 > Ww - 14) jp0 = Ww - 14;

    const int tid  = threadIdx.x;
    const int base = b * (Hh*Ww);

    // stage KV patch (98 tokens x 256 floats)
    for (int f = tid; f < PATCH_TOK*64; f += AT_THREADS) {
        int tok = f >> 6;
        int c4  = f & 63;
        int r   = tok / 14;
        int cc  = tok - r*14;
        int g   = base + (i0 + r)*Ww + (jp0 + cc);
        float4 v = *(const float4*)&kv[(size_t)g*(2*Cc) + c4*4];
        int c = c4*4;
        if (c < Cc) {
            int h = c >> 5, d = c & 31;
            *(float4*)&Ks[(h*PATCH_TOK + tok)*KPAD + d] = v;
        } else {
            int c2 = c - Cc;
            int h = c2 >> 5, d = c2 & 31;
            *(float4*)&Vs[(h*PATCH_TOK + tok)*KPAD + d] = v;
        }
    }
    // stage q (8 queries x 128)
    for (int f = tid; f < 8*32; f += AT_THREADS) {
        int qq = f >> 5, c4 = f & 31;
        int g = base + i*Ww + (jt + qq);
        *(float4*)&qs[qq*Cc + c4*4] = *(const float4*)&q[(size_t)g*Cc + c4*4];
    }
    // stage rpb (4*13*13 = 676)
    for (int f = tid; f < 676; f += AT_THREADS) rs[f] = rpb[f];
    __syncthreads();

    const int w    = tid >> 5;   // 0..15
    const int lane = tid & 31;

    #pragma unroll
    for (int s = 0; s < 2; s++) {
        const int task = w*2 + s;          // 0..31
        const int qq = task >> 2;
        const int h  = task & 3;
        const int j  = jt + qq;
        int j0 = j - 3; if (j0 < 0) j0 = 0; if (j0 > Ww - Kk) j0 = Ww - Kk;
        const int joff = j0 - jp0;

        // q vector in registers
        float4 qv[8];
        #pragma unroll
        for (int u = 0; u < 8; u++)
            qv[u] = *(const float4*)&qs[qq*Cc + h*32 + u*4];

        // scores: lane <-> neighbor (2 rounds, 49 neighbors)
        float sc[2];
        #pragma unroll
        for (int r = 0; r < 2; r++) {
            int n = r*32 + lane;
            float val = -INFINITY;
            if (n < 49) {
                int ni = n / 7;
                int nj = n - ni*7;
                int lt = ni*14 + joff + nj;
                const float* kp = &Ks[(h*PATCH_TOK + lt)*KPAD];
                float a0 = 0.f, a1 = 0.f, a2 = 0.f, a3 = 0.f;
                #pragma unroll
                for (int u = 0; u < 8; u++) {
                    float4 kk4 = *(const float4*)&kp[u*4];
                    a0 = fmaf(qv[u].x, kk4.x, a0);
                    a1 = fmaf(qv[u].y, kk4.y, a1);
                    a2 = fmaf(qv[u].z, kk4.z, a2);
                    a3 = fmaf(qv[u].w, kk4.w, a3);
                }
                int ri = i0 + ni - i + (Kk - 1);
                int rj = j0 + nj - j + (Kk - 1);
                val = ((a0 + a1) + (a2 + a3)) + rs[h*169 + ri*13 + rj];
            }
            sc[r] = val;
        }

        // softmax over 49 within warp
        float mx = fmaxf(sc[0], sc[1]);
        #pragma unroll
        for (int off = 16; off; off >>= 1)
            mx = fmaxf(mx, __shfl_xor_sync(0xffffffff, mx, off));
        float e0 = __expf(sc[0] - mx);
        float e1 = __expf(sc[1] - mx);          // -inf lanes -> 0
        float sum = e0 + e1;
        #pragma unroll
        for (int off = 16; off; off >>= 1)
            sum += __shfl_xor_sync(0xffffffff, sum, off);
        float rinv = 1.0f / sum;
        ps[task*52 + lane] = e0 * rinv;
        if (lane < 17) ps[task*52 + 32 + lane] = e1 * rinv;
        __syncwarp();

        // output: lane <-> dim
        float o = 0.0f;
        #pragma unroll
        for (int n = 0; n < 49; n++) {
            int ni = n / 7;
            int nj = n - ni*7;
            int lt = ni*14 + joff + nj;
            o = fmaf(ps[task*52 + n], Vs[(h*PATCH_TOK + lt)*KPAD + lane], o);
        }
        int g = base + i*Ww + j;
        out[(size_t)g*Cc + h*32 + lane] = o;
        __syncwarp();
    }
}

// ---------------------------------------------------------------------------
// Launch
// ---------------------------------------------------------------------------
extern "C" void kernel_launch(void* const* d_in, const int* in_sizes, int n_in,
                              void* d_out, int out_size)
{
    const float* query     = (const float*)d_in[0];
    const float* key_value = (const float*)d_in[1];
    const float* g1  = (const float*)d_in[2];
    const float* b1  = (const float*)d_in[3];
    const float* g2  = (const float*)d_in[4];
    const float* b2  = (const float*)d_in[5];
    const float* g3  = (const float*)d_in[6];
    const float* b3  = (const float*)d_in[7];
    const float* Wq  = (const float*)d_in[8];
    const float* bq  = (const float*)d_in[9];
    const float* Wkv = (const float*)d_in[10];
    const float* bkv = (const float*)d_in[11];
    const float* Wp  = (const float*)d_in[12];
    const float* bp  = (const float*)d_in[13];
    const float* rpb = (const float*)d_in[14];
    const float* W1  = (const float*)d_in[15];
    const float* bm1 = (const float*)d_in[16];
    const float* W2  = (const float*)d_in[17];
    const float* bm2 = (const float*)d_in[18];
    float* out = (float*)d_out;

    float* qn     = nullptr; cudaGetSymbolAddress((void**)&qn,     g_qn);
    float* kvn    = nullptr; cudaGetSymbolAddress((void**)&kvn,    g_kvn);
    float* qbuf   = nullptr; cudaGetSymbolAddress((void**)&qbuf,   g_q);
    float* kvbuf  = nullptr; cudaGetSymbolAddress((void**)&kvbuf,  g_kv);
    float* attn   = nullptr; cudaGetSymbolAddress((void**)&attn,   g_attn);
    float* xbuf   = nullptr; cudaGetSymbolAddress((void**)&xbuf,   g_x);
    float* hln    = nullptr; cudaGetSymbolAddress((void**)&hln,    g_hln);
    float* hidden = nullptr; cudaGetSymbolAddress((void**)&hidden, g_hidden);

    static bool attr_set = false;
    const int at_smem = (2*4*PATCH_TOK*KPAD + 8*128 + 32*52 + 676) * (int)sizeof(float);
    if (!attr_set) {
        cudaFuncSetAttribute(nat_attn_kernel,
                             cudaFuncAttributeMaxDynamicSharedMemorySize, at_smem);
        attr_set = true;
    }

    const int lnBlocks = (NTOK * 32) / 256;

    // 1) LayerNorms
    ln_kernel<<<lnBlocks, 256>>>(query,     g1, b1, qn,  NTOK);
    ln_kernel<<<lnBlocks, 256>>>(key_value, g2, b2, kvn, NTOK);

    // 2) Q projection (scaled) and KV projection
    gemm_kernel<1><<<dim3(Cc/128,   NTOK/128), 256>>>(qn,  Wq,  bq,  nullptr, qbuf,  NTOK, Cc,   Cc, 0.17677669529663689f);
    gemm_kernel<0><<<dim3(2*Cc/128, NTOK/128), 256>>>(kvn, Wkv, bkv, nullptr, kvbuf, NTOK, 2*Cc, Cc, 1.0f);

    // 3) Neighborhood attention (tiled)
    nat_attn_kernel<<<Bq*Hh*(Ww/8), AT_THREADS, at_smem>>>(qbuf, kvbuf, rpb, attn);

    // 4) Output projection + residual (shortcut = key_value)
    gemm_kernel<3><<<dim3(Cc/128, NTOK/128), 256>>>(attn, Wp, bp, key_value, xbuf, NTOK, Cc, Cc, 1.0f);

    // 5) LN3 + MLP
    ln_kernel<<<lnBlocks, 256>>>(xbuf, g3, b3, hln, NTOK);
    gemm_kernel<2><<<dim3(MLPD/128, NTOK/128), 256>>>(hln,    W1, bm1, nullptr, hidden, NTOK, MLPD, Cc,   1.0f);
    gemm_kernel<3><<<dim3(Cc/128,   NTOK/128), 256>>>(hidden, W2, bm2, xbuf,    out,    NTOK, Cc,   MLPD, 1.0f);
}

// round 3
// speedup vs baseline: 2.0091x; 1.5931x over previous
#include <cuda_runtime.h>
#include <math.h>

// Problem constants
#define Bq  4
#define Hh  64
#define Ww  64
#define Cc  128
#define NHh 4
#define Kk  7
#define HDd 32
#define MLPD 512
#define NTOK (Bq*Hh*Ww)   // 16384

// Scratch (device globals — no allocation allowed in kernel_launch)
__device__ float g_qn    [NTOK*Cc];
__device__ float g_kvn   [NTOK*Cc];
__device__ float g_q     [NTOK*Cc];
__device__ float g_kv    [NTOK*2*Cc];
__device__ float g_attn  [NTOK*Cc];
__device__ float g_x     [NTOK*Cc];
__device__ float g_hln   [NTOK*Cc];
__device__ float g_hidden[NTOK*MLPD];

// ---------------------------------------------------------------------------
// LayerNorm: one warp per token (C=128, lane handles 4 contiguous floats)
// ---------------------------------------------------------------------------
__global__ void ln_kernel(const float* __restrict__ in,
                          const float* __restrict__ g,
                          const float* __restrict__ b,
                          float* __restrict__ out, int ntok)
{
    int warp = (blockIdx.x * blockDim.x + threadIdx.x) >> 5;
    int lane = threadIdx.x & 31;
    if (warp >= ntok) return;

    const float4 v = *(const float4*)&in[(size_t)warp*Cc + lane*4];
    float s  = v.x + v.y + v.z + v.w;
    float sq = v.x*v.x + v.y*v.y + v.z*v.z + v.w*v.w;
    #pragma unroll
    for (int off = 16; off; off >>= 1) {
        s  += __shfl_xor_sync(0xffffffff, s,  off);
        sq += __shfl_xor_sync(0xffffffff, sq, off);
    }
    float mean = s * (1.0f/Cc);
    float var  = sq * (1.0f/Cc) - mean*mean;
    float inv  = rsqrtf(var + 1e-5f);

    const float4 gv = *(const float4*)&g[lane*4];
    const float4 bv = *(const float4*)&b[lane*4];
    float4 o;
    o.x = (v.x - mean)*inv*gv.x + bv.x;
    o.y = (v.y - mean)*inv*gv.y + bv.y;
    o.z = (v.z - mean)*inv*gv.z + bv.z;
    o.w = (v.w - mean)*inv*gv.w + bv.w;
    *(float4*)&out[(size_t)warp*Cc + lane*4] = o;
}

// ---------------------------------------------------------------------------
// TF32 tensor-core GEMM: C = epilogue(A[MxK] @ W[KxN] + bias)
//   MODE 0: +bias
//   MODE 1: (+bias) * scale
//   MODE 2: gelu(+bias)  (exact erf gelu)
//   MODE 3: +bias + residual[MxN]
// CTA 128x128, BK=16 double buffered, 256 threads, 8 warps (4m x 2n),
// warp tile 32x64 via mma.sync m16n8k8 tf32.
// SMEM layouts: As[k][m] pitch 136, Bs[k][n] pitch 136 (conflict-free frags).
// Requires M%128==0, N%128==0, K%16==0.
// ---------------------------------------------------------------------------
#define GP 136   // smem pitch (floats)

__device__ __forceinline__ float f2tf32(float x) {
    float r;
    asm("cvt.rna.tf32.f32 %0, %1;" : "=f"(r) : "f"(x));
    return r;
}

template <int MODE>
__global__ __launch_bounds__(256)
void gemm_tc(const float* __restrict__ A,
             const float* __restrict__ W,
             const float* __restrict__ bias,
             const float* __restrict__ res,
             float* __restrict__ C,
             int M, int N, int K, float scale)
{
    __shared__ float As[2][16*GP];
    __shared__ float Bs[2][16*GP];

    const int tid  = threadIdx.x;
    const int bm   = blockIdx.y * 128;
    const int bn   = blockIdx.x * 128;
    const int warp = tid >> 5;
    const int lane = tid & 31;
    const int g    = lane >> 2;     // group id (0..7)
    const int t    = lane & 3;      // thread in group (0..3)
    const int warpM = warp >> 1;    // 0..3
    const int warpN = warp & 1;     // 0..1
    const int m_base = warpM * 32;
    const int n_base = warpN * 64;

    // global load mapping
    const int ar = tid >> 1;              // A row 0..127
    const int ac = (tid & 1) * 8;         // A k offset 0/8
    const int wr = tid >> 4;              // W k row 0..15
    const int wc = (tid & 15) * 8;        // W n offset 0..120

    const float* Ag = A + (size_t)(bm + ar) * K + ac;
    const float* Wg = W + (size_t)wr * N + bn + wc;

    float acc[2][8][4];
    #pragma unroll
    for (int mt = 0; mt < 2; mt++)
        #pragma unroll
        for (int nt = 0; nt < 8; nt++)
            #pragma unroll
            for (int e = 0; e < 4; e++) acc[mt][nt][e] = 0.0f;

    const int ntile = K / 16;

    float4 av0 = *(const float4*)(Ag);
    float4 av1 = *(const float4*)(Ag + 4);
    float4 bv0 = *(const float4*)(Wg);
    float4 bv1 = *(const float4*)(Wg + 4);

    // stage tile 0
    {
        float* as = As[0];
        as[(ac+0)*GP + ar] = f2tf32(av0.x);
        as[(ac+1)*GP + ar] = f2tf32(av0.y);
        as[(ac+2)*GP + ar] = f2tf32(av0.z);
        as[(ac+3)*GP + ar] = f2tf32(av0.w);
        as[(ac+4)*GP + ar] = f2tf32(av1.x);
        as[(ac+5)*GP + ar] = f2tf32(av1.y);
        as[(ac+6)*GP + ar] = f2tf32(av1.z);
        as[(ac+7)*GP + ar] = f2tf32(av1.w);
        float* bs = Bs[0] + wr*GP + wc;
        float4 c0 = make_float4(f2tf32(bv0.x), f2tf32(bv0.y), f2tf32(bv0.z), f2tf32(bv0.w));
        float4 c1 = make_float4(f2tf32(bv1.x), f2tf32(bv1.y), f2tf32(bv1.z), f2tf32(bv1.w));
        *(float4*)(bs)     = c0;
        *(float4*)(bs + 4) = c1;
    }
    __syncthreads();

    for (int kt = 0; kt < ntile; kt++) {
        const int cur = kt & 1;
        if (kt + 1 < ntile) {
            const float* Ap = Ag + (kt + 1) * 16;
            const float* Wp = Wg + (size_t)(kt + 1) * 16 * N;
            av0 = *(const float4*)(Ap);
            av1 = *(const float4*)(Ap + 4);
            bv0 = *(const float4*)(Wp);
            bv1 = *(const float4*)(Wp + 4);
        }

        const float* as = As[cur];
        const float* bs = Bs[cur];
        #pragma unroll
        for (int kk = 0; kk < 16; kk += 8) {
            unsigned af[2][4], bf[8][2];
            #pragma unroll
            for (int mt = 0; mt < 2; mt++) {
                int m0 = m_base + mt*16 + g;
                af[mt][0] = __float_as_uint(as[(kk+t  )*GP + m0    ]);
                af[mt][1] = __float_as_uint(as[(kk+t  )*GP + m0 + 8]);
                af[mt][2] = __float_as_uint(as[(kk+t+4)*GP + m0    ]);
                af[mt][3] = __float_as_uint(as[(kk+t+4)*GP + m0 + 8]);
            }
            #pragma unroll
            for (int nt = 0; nt < 8; nt++) {
                int n0 = n_base + nt*8 + g;
                bf[nt][0] = __float_as_uint(bs[(kk+t  )*GP + n0]);
                bf[nt][1] = __float_as_uint(bs[(kk+t+4)*GP + n0]);
            }
            #pragma unroll
            for (int mt = 0; mt < 2; mt++)
                #pragma unroll
                for (int nt = 0; nt < 8; nt++)
                    asm volatile(
                        "mma.sync.aligned.m16n8k8.row.col.f32.tf32.tf32.f32 "
                        "{%0,%1,%2,%3}, {%4,%5,%6,%7}, {%8,%9}, {%0,%1,%2,%3};"
                        : "+f"(acc[mt][nt][0]), "+f"(acc[mt][nt][1]),
                          "+f"(acc[mt][nt][2]), "+f"(acc[mt][nt][3])
                        : "r"(af[mt][0]), "r"(af[mt][1]), "r"(af[mt][2]), "r"(af[mt][3]),
                          "r"(bf[nt][0]), "r"(bf[nt][1]));
        }

        if (kt + 1 < ntile) {
            const int nxt = cur ^ 1;
            float* asn = As[nxt];
            asn[(ac+0)*GP + ar] = f2tf32(av0.x);
            asn[(ac+1)*GP + ar] = f2tf32(av0.y);
            asn[(ac+2)*GP + ar] = f2tf32(av0.z);
            asn[(ac+3)*GP + ar] = f2tf32(av0.w);
            asn[(ac+4)*GP + ar] = f2tf32(av1.x);
            asn[(ac+5)*GP + ar] = f2tf32(av1.y);
            asn[(ac+6)*GP + ar] = f2tf32(av1.z);
            asn[(ac+7)*GP + ar] = f2tf32(av1.w);
            float* bsn = Bs[nxt] + wr*GP + wc;
            float4 c0 = make_float4(f2tf32(bv0.x), f2tf32(bv0.y), f2tf32(bv0.z), f2tf32(bv0.w));
            float4 c1 = make_float4(f2tf32(bv1.x), f2tf32(bv1.y), f2tf32(bv1.z), f2tf32(bv1.w));
            *(float4*)(bsn)     = c0;
            *(float4*)(bsn + 4) = c1;
        }
        __syncthreads();
    }

    // epilogue: thread owns rows (g, g+8) per m-tile, cols (2t, 2t+1) per n-tile
    #pragma unroll
    for (int mt = 0; mt < 2; mt++) {
        int row0 = bm + m_base + mt*16 + g;
        int row1 = row0 + 8;
        #pragma unroll
        for (int nt = 0; nt < 8; nt++) {
            int col = bn + n_base + nt*8 + 2*t;
            float b0 = bias[col], b1 = bias[col+1];
            float v00 = acc[mt][nt][0] + b0;
            float v01 = acc[mt][nt][1] + b1;
            float v10 = acc[mt][nt][2] + b0;
            float v11 = acc[mt][nt][3] + b1;
            if (MODE == 1) { v00 *= scale; v01 *= scale; v10 *= scale; v11 *= scale; }
            if (MODE == 2) {
                v00 = 0.5f*v00*(1.0f + erff(v00*0.70710678118654752f));
                v01 = 0.5f*v01*(1.0f + erff(v01*0.70710678118654752f));
                v10 = 0.5f*v10*(1.0f + erff(v10*0.70710678118654752f));
                v11 = 0.5f*v11*(1.0f + erff(v11*0.70710678118654752f));
            }
            if (MODE == 3) {
                float2 r0 = *(const float2*)&res[(size_t)row0*N + col];
                float2 r1 = *(const float2*)&res[(size_t)row1*N + col];
                v00 += r0.x; v01 += r0.y; v10 += r1.x; v11 += r1.y;
            }
            *(float2*)&C[(size_t)row0*N + col] = make_float2(v00, v01);
            *(float2*)&C[(size_t)row1*N + col] = make_float2(v10, v11);
        }
    }
}

// ---------------------------------------------------------------------------
// Neighborhood attention, tiled: one block = 8 queries (same batch, same row i,
// consecutive j), 512 threads. KV patch (7 x 14 tokens, all heads) staged in
// dynamic SMEM once and reused by all 8 queries x 4 heads.
// ---------------------------------------------------------------------------
#define PATCH_TOK 98            // 7 * 14
#define KPAD 36
#define AT_THREADS 512

__global__ __launch_bounds__(AT_THREADS)
void nat_attn_kernel(const float* __restrict__ q,
                     const float* __restrict__ kv,
                     const float* __restrict__ rpb,
                     float* __restrict__ out)
{
    extern __shared__ float sm[];
    float* Ks = sm;                                   // [4][98][36]
    float* Vs = Ks + 4*PATCH_TOK*KPAD;                // [4][98][36]
    float* qs = Vs + 4*PATCH_TOK*KPAD;                // [8][128]
    float* ps = qs + 8*128;                           // [32][52]
    float* rs = ps + 32*52;                           // [676]

    const int blk = blockIdx.x;
    const int b   = blk >> 9;
    const int rem = blk & 511;
    const int i   = rem >> 3;
    const int jt  = (rem & 7) << 3;

    int i0  = i - 3;  if (i0 < 0) i0 = 0;  if (i0 > Hh - Kk) i0 = Hh - Kk;
    int jp0 = jt - 3; if (jp0 < 0) jp0 = 0; if (jp0 > Ww - 14) jp0 = Ww - 14;

    const int tid  = threadIdx.x;
    const int base = b * (Hh*Ww);

    for (int f = tid; f < PATCH_TOK*64; f += AT_THREADS) {
        int tok = f >> 6;
        int c4  = f & 63;
        int r   = tok / 14;
        int cc  = tok - r*14;
        int g   = base + (i0 + r)*Ww + (jp0 + cc);
        float4 v = *(const float4*)&kv[(size_t)g*(2*Cc) + c4*4];
        int c = c4*4;
        if (c < Cc) {
            int h = c >> 5, d = c & 31;
            *(float4*)&Ks[(h*PATCH_TOK + tok)*KPAD + d] = v;
        } else {
            int c2 = c - Cc;
            int h = c2 >> 5, d = c2 & 31;
            *(float4*)&Vs[(h*PATCH_TOK + tok)*KPAD + d] = v;
        }
    }
    for (int f = tid; f < 8*32; f += AT_THREADS) {
        int qq = f >> 5, c4 = f & 31;
        int g = base + i*Ww + (jt + qq);
        *(float4*)&qs[qq*Cc + c4*4] = *(const float4*)&q[(size_t)g*Cc + c4*4];
    }
    for (int f = tid; f < 676; f += AT_THREADS) rs[f] = rpb[f];
    __syncthreads();

    const int w    = tid >> 5;
    const int lane = tid & 31;

    #pragma unroll
    for (int s = 0; s < 2; s++) {
        const int task = w*2 + s;
        const int qq = task >> 2;
        const int h  = task & 3;
        const int j  = jt + qq;
        int j0 = j - 3; if (j0 < 0) j0 = 0; if (j0 > Ww - Kk) j0 = Ww - Kk;
        const int joff = j0 - jp0;

        float4 qv[8];
        #pragma unroll
        for (int u = 0; u < 8; u++)
            qv[u] = *(const float4*)&qs[qq*Cc + h*32 + u*4];

        float sc[2];
        #pragma unroll
        for (int r = 0; r < 2; r++) {
            int n = r*32 + lane;
            float val = -INFINITY;
            if (n < 49) {
                int ni = n / 7;
                int nj = n - ni*7;
                int lt = ni*14 + joff + nj;
                const float* kp = &Ks[(h*PATCH_TOK + lt)*KPAD];
                float a0 = 0.f, a1 = 0.f, a2 = 0.f, a3 = 0.f;
                #pragma unroll
                for (int u = 0; u < 8; u++) {
                    float4 kk4 = *(const float4*)&kp[u*4];
                    a0 = fmaf(qv[u].x, kk4.x, a0);
                    a1 = fmaf(qv[u].y, kk4.y, a1);
                    a2 = fmaf(qv[u].z, kk4.z, a2);
                    a3 = fmaf(qv[u].w, kk4.w, a3);
                }
                int ri = i0 + ni - i + (Kk - 1);
                int rj = j0 + nj - j + (Kk - 1);
                val = ((a0 + a1) + (a2 + a3)) + rs[h*169 + ri*13 + rj];
            }
            sc[r] = val;
        }

        float mx = fmaxf(sc[0], sc[1]);
        #pragma unroll
        for (int off = 16; off; off >>= 1)
            mx = fmaxf(mx, __shfl_xor_sync(0xffffffff, mx, off));
        float e0 = __expf(sc[0] - mx);
        float e1 = __expf(sc[1] - mx);
        float sum = e0 + e1;
        #pragma unroll
        for (int off = 16; off; off >>= 1)
            sum += __shfl_xor_sync(0xffffffff, sum, off);
        float rinv = 1.0f / sum;
        ps[task*52 + lane] = e0 * rinv;
        if (lane < 17) ps[task*52 + 32 + lane] = e1 * rinv;
        __syncwarp();

        float o = 0.0f;
        #pragma unroll
        for (int n = 0; n < 49; n++) {
            int ni = n / 7;
            int nj = n - ni*7;
            int lt = ni*14 + joff + nj;
            o = fmaf(ps[task*52 + n], Vs[(h*PATCH_TOK + lt)*KPAD + lane], o);
        }
        int g = base + i*Ww + j;
        out[(size_t)g*Cc + h*32 + lane] = o;
        __syncwarp();
    }
}

// ---------------------------------------------------------------------------
// Launch
// ---------------------------------------------------------------------------
extern "C" void kernel_launch(void* const* d_in, const int* in_sizes, int n_in,
                              void* d_out, int out_size)
{
    const float* query     = (const float*)d_in[0];
    const float* key_value = (const float*)d_in[1];
    const float* g1  = (const float*)d_in[2];
    const float* b1  = (const float*)d_in[3];
    const float* g2  = (const float*)d_in[4];
    const float* b2  = (const float*)d_in[5];
    const float* g3  = (const float*)d_in[6];
    const float* b3  = (const float*)d_in[7];
    const float* Wq  = (const float*)d_in[8];
    const float* bq  = (const float*)d_in[9];
    const float* Wkv = (const float*)d_in[10];
    const float* bkv = (const float*)d_in[11];
    const float* Wp  = (const float*)d_in[12];
    const float* bp  = (const float*)d_in[13];
    const float* rpb = (const float*)d_in[14];
    const float* W1  = (const float*)d_in[15];
    const float* bm1 = (const float*)d_in[16];
    const float* W2  = (const float*)d_in[17];
    const float* bm2 = (const float*)d_in[18];
    float* out = (float*)d_out;

    float* qn     = nullptr; cudaGetSymbolAddress((void**)&qn,     g_qn);
    float* kvn    = nullptr; cudaGetSymbolAddress((void**)&kvn,    g_kvn);
    float* qbuf   = nullptr; cudaGetSymbolAddress((void**)&qbuf,   g_q);
    float* kvbuf  = nullptr; cudaGetSymbolAddress((void**)&kvbuf,  g_kv);
    float* attn   = nullptr; cudaGetSymbolAddress((void**)&attn,   g_attn);
    float* xbuf   = nullptr; cudaGetSymbolAddress((void**)&xbuf,   g_x);
    float* hln    = nullptr; cudaGetSymbolAddress((void**)&hln,    g_hln);
    float* hidden = nullptr; cudaGetSymbolAddress((void**)&hidden, g_hidden);

    static bool attr_set = false;
    const int at_smem = (2*4*PATCH_TOK*KPAD + 8*128 + 32*52 + 676) * (int)sizeof(float);
    if (!attr_set) {
        cudaFuncSetAttribute(nat_attn_kernel,
                             cudaFuncAttributeMaxDynamicSharedMemorySize, at_smem);
        attr_set = true;
    }

    const int lnBlocks = (NTOK * 32) / 256;

    // 1) LayerNorms
    ln_kernel<<<lnBlocks, 256>>>(query,     g1, b1, qn,  NTOK);
    ln_kernel<<<lnBlocks, 256>>>(key_value, g2, b2, kvn, NTOK);

    // 2) Q projection (scaled) and KV projection — tf32 tensor cores
    gemm_tc<1><<<dim3(Cc/128,   NTOK/128), 256>>>(qn,  Wq,  bq,  nullptr, qbuf,  NTOK, Cc,   Cc, 0.17677669529663689f);
    gemm_tc<0><<<dim3(2*Cc/128, NTOK/128), 256>>>(kvn, Wkv, bkv, nullptr, kvbuf, NTOK, 2*Cc, Cc, 1.0f);

    // 3) Neighborhood attention (tiled)
    nat_attn_kernel<<<Bq*Hh*(Ww/8), AT_THREADS, at_smem>>>(qbuf, kvbuf, rpb, attn);

    // 4) Output projection + residual (shortcut = key_value)
    gemm_tc<3><<<dim3(Cc/128, NTOK/128), 256>>>(attn, Wp, bp, key_value, xbuf, NTOK, Cc, Cc, 1.0f);

    // 5) LN3 + MLP
    ln_kernel<<<lnBlocks, 256>>>(xbuf, g3, b3, hln, NTOK);
    gemm_tc<2><<<dim3(MLPD/128, NTOK/128), 256>>>(hln,    W1, bm1, nullptr, hidden, NTOK, MLPD, Cc,   1.0f);
    gemm_tc<3><<<dim3(Cc/128,   NTOK/128), 256>>>(hidden, W2, bm2, xbuf,    out,    NTOK, Cc,   MLPD, 1.0f);
}

// round 4
// speedup vs baseline: 2.0453x; 1.0180x over previous
#include <cuda_runtime.h>
#include <math.h>

// Problem constants
#define Bq  4
#define Hh  64
#define Ww  64
#define Cc  128
#define NHh 4
#define Kk  7
#define HDd 32
#define MLPD 512
#define NTOK (Bq*Hh*Ww)   // 16384

// Scratch (device globals — no allocation allowed in kernel_launch)
__device__ float g_qn    [NTOK*Cc];
__device__ float g_kvn   [NTOK*Cc];
__device__ float g_q     [NTOK*Cc];
__device__ float g_kv    [NTOK*2*Cc];
__device__ float g_attn  [NTOK*Cc];
__device__ float g_x     [NTOK*Cc];
__device__ float g_hln   [NTOK*Cc];
__device__ float g_hidden[NTOK*MLPD];

// ---------------------------------------------------------------------------
// LayerNorm: one warp per token (C=128, lane handles 4 contiguous floats)
// ---------------------------------------------------------------------------
__global__ void ln_kernel(const float* __restrict__ in,
                          const float* __restrict__ g,
                          const float* __restrict__ b,
                          float* __restrict__ out, int ntok)
{
    int warp = (blockIdx.x * blockDim.x + threadIdx.x) >> 5;
    int lane = threadIdx.x & 31;
    if (warp >= ntok) return;

    const float4 v = *(const float4*)&in[(size_t)warp*Cc + lane*4];
    float s  = v.x + v.y + v.z + v.w;
    float sq = v.x*v.x + v.y*v.y + v.z*v.z + v.w*v.w;
    #pragma unroll
    for (int off = 16; off; off >>= 1) {
        s  += __shfl_xor_sync(0xffffffff, s,  off);
        sq += __shfl_xor_sync(0xffffffff, sq, off);
    }
    float mean = s * (1.0f/Cc);
    float var  = sq * (1.0f/Cc) - mean*mean;
    float inv  = rsqrtf(var + 1e-5f);

    const float4 gv = *(const float4*)&g[lane*4];
    const float4 bv = *(const float4*)&b[lane*4];
    float4 o;
    o.x = (v.x - mean)*inv*gv.x + bv.x;
    o.y = (v.y - mean)*inv*gv.y + bv.y;
    o.z = (v.z - mean)*inv*gv.z + bv.z;
    o.w = (v.w - mean)*inv*gv.w + bv.w;
    *(float4*)&out[(size_t)warp*Cc + lane*4] = o;
}

// ---------------------------------------------------------------------------
// TF32 tensor-core GEMM: C = epilogue(A[MxK] @ W[KxN] + bias)
//   MODE 0: +bias
//   MODE 1: (+bias) * scale
//   MODE 2: gelu(+bias)  (exact erf gelu)
//   MODE 3: +bias + residual[MxN]
// CTA 128x128, BK=16 double buffered, 256 threads, 8 warps (4m x 2n),
// warp tile 32x64 via mma.sync m16n8k8 tf32.
// SMEM layouts: As[k][m] pitch 136, Bs[k][n] pitch 136 (conflict-free frags).
// Requires M%128==0, N%128==0, K%16==0.
// ---------------------------------------------------------------------------
#define GP 136   // smem pitch (floats)

__device__ __forceinline__ float f2tf32(float x) {
    float r;
    asm("cvt.rna.tf32.f32 %0, %1;" : "=f"(r) : "f"(x));
    return r;
}

template <int MODE>
__global__ __launch_bounds__(256)
void gemm_tc(const float* __restrict__ A,
             const float* __restrict__ W,
             const float* __restrict__ bias,
             const float* __restrict__ res,
             float* __restrict__ C,
             int M, int N, int K, float scale)
{
    __shared__ float As[2][16*GP];
    __shared__ float Bs[2][16*GP];

    const int tid  = threadIdx.x;
    const int bm   = blockIdx.y * 128;
    const int bn   = blockIdx.x * 128;
    const int warp = tid >> 5;
    const int lane = tid & 31;
    const int g    = lane >> 2;     // group id (0..7)
    const int t    = lane & 3;      // thread in group (0..3)
    const int warpM = warp >> 1;    // 0..3
    const int warpN = warp & 1;     // 0..1
    const int m_base = warpM * 32;
    const int n_base = warpN * 64;

    // global load mapping
    const int ar = tid >> 1;              // A row 0..127
    const int ac = (tid & 1) * 8;         // A k offset 0/8
    const int wr = tid >> 4;              // W k row 0..15
    const int wc = (tid & 15) * 8;        // W n offset 0..120

    const float* Ag = A + (size_t)(bm + ar) * K + ac;
    const float* Wg = W + (size_t)wr * N + bn + wc;

    float acc[2][8][4];
    #pragma unroll
    for (int mt = 0; mt < 2; mt++)
        #pragma unroll
        for (int nt = 0; nt < 8; nt++)
            #pragma unroll
            for (int e = 0; e < 4; e++) acc[mt][nt][e] = 0.0f;

    const int ntile = K / 16;

    float4 av0 = *(const float4*)(Ag);
    float4 av1 = *(const float4*)(Ag + 4);
    float4 bv0 = *(const float4*)(Wg);
    float4 bv1 = *(const float4*)(Wg + 4);

    // stage tile 0
    {
        float* as = As[0];
        as[(ac+0)*GP + ar] = f2tf32(av0.x);
        as[(ac+1)*GP + ar] = f2tf32(av0.y);
        as[(ac+2)*GP + ar] = f2tf32(av0.z);
        as[(ac+3)*GP + ar] = f2tf32(av0.w);
        as[(ac+4)*GP + ar] = f2tf32(av1.x);
        as[(ac+5)*GP + ar] = f2tf32(av1.y);
        as[(ac+6)*GP + ar] = f2tf32(av1.z);
        as[(ac+7)*GP + ar] = f2tf32(av1.w);
        float* bs = Bs[0] + wr*GP + wc;
        float4 c0 = make_float4(f2tf32(bv0.x), f2tf32(bv0.y), f2tf32(bv0.z), f2tf32(bv0.w));
        float4 c1 = make_float4(f2tf32(bv1.x), f2tf32(bv1.y), f2tf32(bv1.z), f2tf32(bv1.w));
        *(float4*)(bs)     = c0;
        *(float4*)(bs + 4) = c1;
    }
    __syncthreads();

    for (int kt = 0; kt < ntile; kt++) {
        const int cur = kt & 1;
        if (kt + 1 < ntile) {
            const float* Ap = Ag + (kt + 1) * 16;
            const float* Wp = Wg + (size_t)(kt + 1) * 16 * N;
            av0 = *(const float4*)(Ap);
            av1 = *(const float4*)(Ap + 4);
            bv0 = *(const float4*)(Wp);
            bv1 = *(const float4*)(Wp + 4);
        }

        const float* as = As[cur];
        const float* bs = Bs[cur];
        #pragma unroll
        for (int kk = 0; kk < 16; kk += 8) {
            unsigned af[2][4], bf[8][2];
            #pragma unroll
            for (int mt = 0; mt < 2; mt++) {
                int m0 = m_base + mt*16 + g;
                af[mt][0] = __float_as_uint(as[(kk+t  )*GP + m0    ]);
                af[mt][1] = __float_as_uint(as[(kk+t  )*GP + m0 + 8]);
                af[mt][2] = __float_as_uint(as[(kk+t+4)*GP + m0    ]);
                af[mt][3] = __float_as_uint(as[(kk+t+4)*GP + m0 + 8]);
            }
            #pragma unroll
            for (int nt = 0; nt < 8; nt++) {
                int n0 = n_base + nt*8 + g;
                bf[nt][0] = __float_as_uint(bs[(kk+t  )*GP + n0]);
                bf[nt][1] = __float_as_uint(bs[(kk+t+4)*GP + n0]);
            }
            #pragma unroll
            for (int mt = 0; mt < 2; mt++)
                #pragma unroll
                for (int nt = 0; nt < 8; nt++)
                    asm volatile(
                        "mma.sync.aligned.m16n8k8.row.col.f32.tf32.tf32.f32 "
                        "{%0,%1,%2,%3}, {%4,%5,%6,%7}, {%8,%9}, {%0,%1,%2,%3};"
                        : "+f"(acc[mt][nt][0]), "+f"(acc[mt][nt][1]),
                          "+f"(acc[mt][nt][2]), "+f"(acc[mt][nt][3])
                        : "r"(af[mt][0]), "r"(af[mt][1]), "r"(af[mt][2]), "r"(af[mt][3]),
                          "r"(bf[nt][0]), "r"(bf[nt][1]));
        }

        if (kt + 1 < ntile) {
            const int nxt = cur ^ 1;
            float* asn = As[nxt];
            asn[(ac+0)*GP + ar] = f2tf32(av0.x);
            asn[(ac+1)*GP + ar] = f2tf32(av0.y);
            asn[(ac+2)*GP + ar] = f2tf32(av0.z);
            asn[(ac+3)*GP + ar] = f2tf32(av0.w);
            asn[(ac+4)*GP + ar] = f2tf32(av1.x);
            asn[(ac+5)*GP + ar] = f2tf32(av1.y);
            asn[(ac+6)*GP + ar] = f2tf32(av1.z);
            asn[(ac+7)*GP + ar] = f2tf32(av1.w);
            float* bsn = Bs[nxt] + wr*GP + wc;
            float4 c0 = make_float4(f2tf32(bv0.x), f2tf32(bv0.y), f2tf32(bv0.z), f2tf32(bv0.w));
            float4 c1 = make_float4(f2tf32(bv1.x), f2tf32(bv1.y), f2tf32(bv1.z), f2tf32(bv1.w));
            *(float4*)(bsn)     = c0;
            *(float4*)(bsn + 4) = c1;
        }
        __syncthreads();
    }

    // epilogue: thread owns rows (g, g+8) per m-tile, cols (2t, 2t+1) per n-tile
    #pragma unroll
    for (int mt = 0; mt < 2; mt++) {
        int row0 = bm + m_base + mt*16 + g;
        int row1 = row0 + 8;
        #pragma unroll
        for (int nt = 0; nt < 8; nt++) {
            int col = bn + n_base + nt*8 + 2*t;
            float b0 = bias[col], b1 = bias[col+1];
            float v00 = acc[mt][nt][0] + b0;
            float v01 = acc[mt][nt][1] + b1;
            float v10 = acc[mt][nt][2] + b0;
            float v11 = acc[mt][nt][3] + b1;
            if (MODE == 1) { v00 *= scale; v01 *= scale; v10 *= scale; v11 *= scale; }
            if (MODE == 2) {
                v00 = 0.5f*v00*(1.0f + erff(v00*0.70710678118654752f));
                v01 = 0.5f*v01*(1.0f + erff(v01*0.70710678118654752f));
                v10 = 0.5f*v10*(1.0f + erff(v10*0.70710678118654752f));
                v11 = 0.5f*v11*(1.0f + erff(v11*0.70710678118654752f));
            }
            if (MODE == 3) {
                float2 r0 = *(const float2*)&res[(size_t)row0*N + col];
                float2 r1 = *(const float2*)&res[(size_t)row1*N + col];
                v00 += r0.x; v01 += r0.y; v10 += r1.x; v11 += r1.y;
            }
            *(float2*)&C[(size_t)row0*N + col] = make_float2(v00, v01);
            *(float2*)&C[(size_t)row1*N + col] = make_float2(v10, v11);
        }
    }
}

// ---------------------------------------------------------------------------
// Neighborhood attention, tiled: one block = 8 queries (same batch, same row i,
// consecutive j), 512 threads. KV patch (7 x 14 tokens, all heads) staged in
// dynamic SMEM once and reused by all 8 queries x 4 heads.
// ---------------------------------------------------------------------------
#define PATCH_TOK 98            // 7 * 14
#define KPAD 36
#define AT_THREADS 512

__global__ __launch_bounds__(AT_THREADS)
void nat_attn_kernel(const float* __restrict__ q,
                     const float* __restrict__ kv,
                     const float* __restrict__ rpb,
                     float* __restrict__ out)
{
    extern __shared__ float sm[];
    float* Ks = sm;                                   // [4][98][36]
    float* Vs = Ks + 4*PATCH_TOK*KPAD;                // [4][98][36]
    float* qs = Vs + 4*PATCH_TOK*KPAD;                // [8][128]
    float* ps = qs + 8*128;                           // [32][52]
    float* rs = ps + 32*52;                           // [676]

    const int blk = blockIdx.x;
    const int b   = blk >> 9;
    const int rem = blk & 511;
    const int i   = rem >> 3;
    const int jt  = (rem & 7) << 3;

    int i0  = i - 3;  if (i0 < 0) i0 = 0;  if (i0 > Hh - Kk) i0 = Hh - Kk;
    int jp0 = jt - 3; if (jp0 < 0) jp0 = 0; if (jp0 > Ww - 14) jp0 = Ww - 14;

    const int tid  = threadIdx.x;
    const int base = b * (Hh*Ww);

    for (int f = tid; f < PATCH_TOK*64; f += AT_THREADS) {
        int tok = f >> 6;
        int c4  = f & 63;
        int r   = tok / 14;
        int cc  = tok - r*14;
        int g   = base + (i0 + r)*Ww + (jp0 + cc);
        float4 v = *(const float4*)&kv[(size_t)g*(2*Cc) + c4*4];
        int c = c4*4;
        if (c < Cc) {
            int h = c >> 5, d = c & 31;
            *(float4*)&Ks[(h*PATCH_TOK + tok)*KPAD + d] = v;
        } else {
            int c2 = c - Cc;
            int h = c2 >> 5, d = c2 & 31;
            *(float4*)&Vs[(h*PATCH_TOK + tok)*KPAD + d] = v;
        }
    }
    for (int f = tid; f < 8*32; f += AT_THREADS) {
        int qq = f >> 5, c4 = f & 31;
        int g = base + i*Ww + (jt + qq);
        *(float4*)&qs[qq*Cc + c4*4] = *(const float4*)&q[(size_t)g*Cc + c4*4];
    }
    for (int f = tid; f < 676; f += AT_THREADS) rs[f] = rpb[f];
    __syncthreads();

    const int w    = tid >> 5;
    const int lane = tid & 31;

    #pragma unroll
    for (int s = 0; s < 2; s++) {
        const int task = w*2 + s;
        const int qq = task >> 2;
        const int h  = task & 3;
        const int j  = jt + qq;
        int j0 = j - 3; if (j0 < 0) j0 = 0; if (j0 > Ww - Kk) j0 = Ww - Kk;
        const int joff = j0 - jp0;

        float4 qv[8];
        #pragma unroll
        for (int u = 0; u < 8; u++)
            qv[u] = *(const float4*)&qs[qq*Cc + h*32 + u*4];

        float sc[2];
        #pragma unroll
        for (int r = 0; r < 2; r++) {
            int n = r*32 + lane;
            float val = -INFINITY;
            if (n < 49) {
                int ni = n / 7;
                int nj = n - ni*7;
                int lt = ni*14 + joff + nj;
                const float* kp = &Ks[(h*PATCH_TOK + lt)*KPAD];
                float a0 = 0.f, a1 = 0.f, a2 = 0.f, a3 = 0.f;
                #pragma unroll
                for (int u = 0; u < 8; u++) {
                    float4 kk4 = *(const float4*)&kp[u*4];
                    a0 = fmaf(qv[u].x, kk4.x, a0);
                    a1 = fmaf(qv[u].y, kk4.y, a1);
                    a2 = fmaf(qv[u].z, kk4.z, a2);
                    a3 = fmaf(qv[u].w, kk4.w, a3);
                }
                int ri = i0 + ni - i + (Kk - 1);
                int rj = j0 + nj - j + (Kk - 1);
                val = ((a0 + a1) + (a2 + a3)) + rs[h*169 + ri*13 + rj];
            }
            sc[r] = val;
        }

        float mx = fmaxf(sc[0], sc[1]);
        #pragma unroll
        for (int off = 16; off; off >>= 1)
            mx = fmaxf(mx, __shfl_xor_sync(0xffffffff, mx, off));
        float e0 = __expf(sc[0] - mx);
        float e1 = __expf(sc[1] - mx);
        float sum = e0 + e1;
        #pragma unroll
        for (int off = 16; off; off >>= 1)
            sum += __shfl_xor_sync(0xffffffff, sum, off);
        float rinv = 1.0f / sum;
        ps[task*52 + lane] = e0 * rinv;
        if (lane < 17) ps[task*52 + 32 + lane] = e1 * rinv;
        __syncwarp();

        float o = 0.0f;
        #pragma unroll
        for (int n = 0; n < 49; n++) {
            int ni = n / 7;
            int nj = n - ni*7;
            int lt = ni*14 + joff + nj;
            o = fmaf(ps[task*52 + n], Vs[(h*PATCH_TOK + lt)*KPAD + lane], o);
        }
        int g = base + i*Ww + j;
        out[(size_t)g*Cc + h*32 + lane] = o;
        __syncwarp();
    }
}

// ---------------------------------------------------------------------------
// Launch
// ---------------------------------------------------------------------------
extern "C" void kernel_launch(void* const* d_in, const int* in_sizes, int n_in,
                              void* d_out, int out_size)
{
    const float* query     = (const float*)d_in[0];
    const float* key_value = (const float*)d_in[1];
    const float* g1  = (const float*)d_in[2];
    const float* b1  = (const float*)d_in[3];
    const float* g2  = (const float*)d_in[4];
    const float* b2  = (const float*)d_in[5];
    const float* g3  = (const float*)d_in[6];
    const float* b3  = (const float*)d_in[7];
    const float* Wq  = (const float*)d_in[8];
    const float* bq  = (const float*)d_in[9];
    const float* Wkv = (const float*)d_in[10];
    const float* bkv = (const float*)d_in[11];
    const float* Wp  = (const float*)d_in[12];
    const float* bp  = (const float*)d_in[13];
    const float* rpb = (const float*)d_in[14];
    const float* W1  = (const float*)d_in[15];
    const float* bm1 = (const float*)d_in[16];
    const float* W2  = (const float*)d_in[17];
    const float* bm2 = (const float*)d_in[18];
    float* out = (float*)d_out;

    float* qn     = nullptr; cudaGetSymbolAddress((void**)&qn,     g_qn);
    float* kvn    = nullptr; cudaGetSymbolAddress((void**)&kvn,    g_kvn);
    float* qbuf   = nullptr; cudaGetSymbolAddress((void**)&qbuf,   g_q);
    float* kvbuf  = nullptr; cudaGetSymbolAddress((void**)&kvbuf,  g_kv);
    float* attn   = nullptr; cudaGetSymbolAddress((void**)&attn,   g_attn);
    float* xbuf   = nullptr; cudaGetSymbolAddress((void**)&xbuf,   g_x);
    float* hln    = nullptr; cudaGetSymbolAddress((void**)&hln,    g_hln);
    float* hidden = nullptr; cudaGetSymbolAddress((void**)&hidden, g_hidden);

    static bool attr_set = false;
    const int at_smem = (2*4*PATCH_TOK*KPAD + 8*128 + 32*52 + 676) * (int)sizeof(float);
    if (!attr_set) {
        cudaFuncSetAttribute(nat_attn_kernel,
                             cudaFuncAttributeMaxDynamicSharedMemorySize, at_smem);
        attr_set = true;
    }

    const int lnBlocks = (NTOK * 32) / 256;

    // 1) LayerNorms
    ln_kernel<<<lnBlocks, 256>>>(query,     g1, b1, qn,  NTOK);
    ln_kernel<<<lnBlocks, 256>>>(key_value, g2, b2, kvn, NTOK);

    // 2) Q projection (scaled) and KV projection — tf32 tensor cores
    gemm_tc<1><<<dim3(Cc/128,   NTOK/128), 256>>>(qn,  Wq,  bq,  nullptr, qbuf,  NTOK, Cc,   Cc, 0.17677669529663689f);
    gemm_tc<0><<<dim3(2*Cc/128, NTOK/128), 256>>>(kvn, Wkv, bkv, nullptr, kvbuf, NTOK, 2*Cc, Cc, 1.0f);

    // 3) Neighborhood attention (tiled)
    nat_attn_kernel<<<Bq*Hh*(Ww/8), AT_THREADS, at_smem>>>(qbuf, kvbuf, rpb, attn);

    // 4) Output projection + residual (shortcut = key_value)
    gemm_tc<3><<<dim3(Cc/128, NTOK/128), 256>>>(attn, Wp, bp, key_value, xbuf, NTOK, Cc, Cc, 1.0f);

    // 5) LN3 + MLP
    ln_kernel<<<lnBlocks, 256>>>(xbuf, g3, b3, hln, NTOK);
    gemm_tc<2><<<dim3(MLPD/128, NTOK/128), 256>>>(hln,    W1, bm1, nullptr, hidden, NTOK, MLPD, Cc,   1.0f);
    gemm_tc<3><<<dim3(Cc/128,   NTOK/128), 256>>>(hidden, W2, bm2, xbuf,    out,    NTOK, Cc,   MLPD, 1.0f);
}